// round 6
// baseline (speedup 1.0000x reference)
#include <cuda_runtime.h>
#include <cuda_fp16.h>
#include <math.h>
#include <stdint.h>

#define BB 8
#define CC 256
#define NN 4096      // H*W
#define GG 32
#define CPG 8
#define EPSV 1e-5f

// GEMM tiling (fp16 operands, fp32 accum)
#define BM 128
#define BN 256
#define BKH 32                         // K per stage, in half elements
#define PADH 8
#define ROWH (BKH + PADH)              // 40 half = 80 B
#define A_STG_H (BM * ROWH)            // 5120 half
#define B_STG_H (BN * ROWH)            // 10240 half
#define STG_H (A_STG_H + B_STG_H)      // 15360 half = 30720 B
#define NSTAGE 3
#define SMEM_BYTES (NSTAGE * STG_H * 2)  // 92160 B
#define NTILES (NN / BN)               // 16 n-tiles in QK

// ---------------- scratch (device globals) -----------------------------------
__device__ float  g_mean[BB * GG];
__device__ float  g_rstd[BB * GG];
__device__ __half g_qT   [(size_t)BB * NN * CC];   // Q^T  [b][n][c], scaled
__device__ __half g_normT[(size_t)BB * NN * CC];   // GN(x)^T [b][n][c]
__device__ __half g_keyT [(size_t)BB * NN * CC];   // K^T  [b][n][c]
__device__ __half g_val  [(size_t)BB * CC * NN];   // V    [b][c][n]
__device__ __half g_attn [(size_t)BB * NN * NN];   // S    [b][m][n]  256 MB
__device__ __half g_aoT  [(size_t)BB * NN * CC];   // AO^T [b][n][c]
__device__ __half g_wkv_h[2 * CC * CC];
__device__ __half g_wout_h[CC * CC];
__device__ float  g_Mt  [(size_t)BB * NTILES * NN];  // per-tile row max
__device__ float  g_Lt  [(size_t)BB * NTILES * NN];  // per-tile row sumexp
__device__ float  g_M   [(size_t)BB * NN];           // final row max
__device__ float  g_Linv[(size_t)BB * NN];           // 1 / row sumexp

// ---------------- 1. GroupNorm statistics ------------------------------------
__global__ void gn_stats(const float* __restrict__ x) {
    const int bg = blockIdx.x;
    const float* p = x + (size_t)bg * (CPG * NN);
    const int tid = threadIdx.x;
    float s = 0.f, s2 = 0.f;
    for (int i = tid; i < CPG * NN; i += 256) {
        float v = p[i];
        s += v; s2 += v * v;
    }
    __shared__ float sh[256], sh2[256];
    sh[tid] = s; sh2[tid] = s2;
    __syncthreads();
    for (int o = 128; o > 0; o >>= 1) {
        if (tid < o) { sh[tid] += sh[tid + o]; sh2[tid] += sh2[tid + o]; }
        __syncthreads();
    }
    if (tid == 0) {
        const float inv_n = 1.f / (CPG * NN);
        float m   = sh[0] * inv_n;
        float var = sh2[0] * inv_n - m * m;
        g_mean[bg] = m;
        g_rstd[bg] = rsqrtf(var + EPSV);
    }
}

// ---------------- 2. weights -> fp16 -----------------------------------------
__global__ void round_w(const float* __restrict__ wkv,
                        const float* __restrict__ wout) {
    int i = blockIdx.x * 256 + threadIdx.x;
    if (i < 2 * CC * CC) g_wkv_h[i] = __float2half_rn(wkv[i]);
    if (i < CC * CC)     g_wout_h[i] = __float2half_rn(wout[i]);
}

// ---------------- 3. Q projection, transposed + scaled -> fp16 ---------------
__global__ void q_proj_t(const float* __restrict__ qin,   // [B,3,N]
                         const float* __restrict__ wq) {  // [C,3]
    size_t idx = (size_t)blockIdx.x * 256 + threadIdx.x;
    if (idx >= (size_t)BB * NN * CC) return;
    int c = (int)(idx & (CC - 1));
    int n = (int)((idx >> 8) & (NN - 1));
    int b = (int)(idx >> 20);
    const float* qb = qin + (size_t)b * 3 * NN + n;
    g_qT[idx] = __float2half_rn(0.0625f * (wq[c * 3 + 0] * qb[0]
                                         + wq[c * 3 + 1] * qb[NN]
                                         + wq[c * 3 + 2] * qb[2 * NN]));
}

// ---------------- 4. GroupNorm apply + transpose -> fp16 ---------------------
__global__ void __launch_bounds__(256) norm_t(const float* __restrict__ x,
                                              const float* __restrict__ gamma,
                                              const float* __restrict__ beta) {
    __shared__ float t[32][33];
    const int b  = blockIdx.z;
    const int n0 = blockIdx.x * 32, c0 = blockIdx.y * 32;
    const int tx = threadIdx.x, ty = threadIdx.y;
#pragma unroll
    for (int i = 0; i < 4; i++) {
        int c  = c0 + ty + i * 8;
        int bg = b * GG + (c >> 3);
        float sc = g_rstd[bg] * gamma[c];
        float sh = beta[c] - g_mean[bg] * sc;
        float v = x[((size_t)b * CC + c) * NN + n0 + tx];
        t[ty + i * 8][tx] = v * sc + sh;
    }
    __syncthreads();
#pragma unroll
    for (int i = 0; i < 4; i++) {
        int n = n0 + ty + i * 8;
        g_normT[((size_t)b * NN + n) * CC + c0 + tx] =
            __float2half_rn(t[tx][ty + i * 8]);
    }
}

// ---------------- generic TN fp16 tensor-core GEMM (cp.async, 3-stage) -------
// C[m][n] = sum_k A[m][k] * B[n][k]; A,B fp16 k-contiguous.
// mode 0: fp32 out + bias + resid
// mode 1: fp16 out
// mode 2: KV split -> keyT (transposed) + val
// mode 3: fp16 out + per-tile softmax stats (Mt/Lt) [QK]
// mode 4: A := exp(A - M[row]) in-fragment, out fp16 scaled by Linv[row] [PV]
#define CP16(d, s) asm volatile("cp.async.cg.shared.global [%0], [%1], 16;" :: "r"(d), "l"(s))

__global__ void __launch_bounds__(256) gemm_tn_f16(
    const __half* __restrict__ Ag, const __half* __restrict__ Bg,
    void* __restrict__ Cg, __half* __restrict__ Ct,
    const float* __restrict__ bias, const float* __restrict__ resid,
    int K, int ldc, int ldct, int mode,
    size_t sA, size_t sB, size_t sC, size_t sCt, size_t sR)
{
    extern __shared__ __half sm[];
    const int b = blockIdx.z;
    const __half* A = Ag + (size_t)b * sA;
    const __half* B = Bg + (size_t)b * sB;
    const int m0 = blockIdx.y * BM;
    const int n0 = blockIdx.x * BN;

    const int tid  = threadIdx.x;
    const int lane = tid & 31;
    const int warp = tid >> 5;
    const int wm = (warp & 1) * 64;
    const int wn = (warp >> 1) * 64;
    const int g = lane >> 2, t = lane & 3;

    // cp.async mapping: 4 threads/row, 16B (8 half) each
    const int r4 = tid >> 2;           // 0..63
    const int c8 = (tid & 3) * 8;      // half offset within row
    const __half* Ap = A + (size_t)(m0 + r4) * K + c8;
    const __half* Bp = B + (size_t)(n0 + r4) * K + c8;
    const uint32_t sbase = (uint32_t)__cvta_generic_to_shared(sm);

#define ISSUE(s, ko)                                                          \
    do {                                                                      \
        uint32_t as_ = sbase + (uint32_t)(s) * (STG_H * 2);                   \
        uint32_t bs_ = as_ + A_STG_H * 2;                                     \
        const __half* ap_ = Ap + (ko);                                        \
        const __half* bp_ = Bp + (ko);                                        \
        CP16(as_ + (r4 * ROWH + c8) * 2,         ap_);                        \
        CP16(as_ + ((r4 + 64) * ROWH + c8) * 2,  ap_ + (size_t)64 * K);       \
        CP16(bs_ + (r4 * ROWH + c8) * 2,         bp_);                        \
        CP16(bs_ + ((r4 + 64) * ROWH + c8) * 2,  bp_ + (size_t)64 * K);       \
        CP16(bs_ + ((r4 + 128) * ROWH + c8) * 2, bp_ + (size_t)128 * K);      \
        CP16(bs_ + ((r4 + 192) * ROWH + c8) * 2, bp_ + (size_t)192 * K);      \
        asm volatile("cp.async.commit_group;");                               \
    } while (0)

    // mode 4: preload per-row max (rows constant over k)
    float Mreg[4][2];
    if (mode == 4) {
#pragma unroll
        for (int mi = 0; mi < 4; mi++) {
            int r = m0 + wm + mi * 16 + g;
            Mreg[mi][0] = g_M[(size_t)b * NN + r];
            Mreg[mi][1] = g_M[(size_t)b * NN + r + 8];
        }
    }

    float acc[4][8][4];
#pragma unroll
    for (int mi = 0; mi < 4; mi++)
#pragma unroll
        for (int ni = 0; ni < 8; ni++)
#pragma unroll
            for (int r = 0; r < 4; r++) acc[mi][ni][r] = 0.f;

    const int iters = K / BKH;         // >= 8 always
    ISSUE(0, 0);
    ISSUE(1, BKH);

    int stage = 0;
    for (int it = 0; it < iters; ++it) {
        if (it + 2 < iters) {
            int s2 = stage + 2; if (s2 >= NSTAGE) s2 -= NSTAGE;
            ISSUE(s2, (size_t)(it + 2) * BKH);
            asm volatile("cp.async.wait_group 2;");
        } else if (it + 1 < iters) {
            asm volatile("cp.async.wait_group 1;");
        } else {
            asm volatile("cp.async.wait_group 0;");
        }
        __syncthreads();

        const uint32_t* As = (const uint32_t*)(sm + stage * STG_H);
        const uint32_t* Bs = As + (A_STG_H >> 1);

#pragma unroll
        for (int kk = 0; kk < 2; kk++) {            // two k16 steps
            uint32_t af[4][4], bf[8][2];
#pragma unroll
            for (int mi = 0; mi < 4; mi++) {
                const uint32_t* p = As + (wm + mi * 16 + g) * (ROWH / 2) + kk * 8 + t;
                af[mi][0] = p[0];
                af[mi][1] = p[8 * (ROWH / 2)];
                af[mi][2] = p[4];
                af[mi][3] = p[8 * (ROWH / 2) + 4];
            }
            if (mode == 4) {
                // A := exp(A - M[row]) applied in-register
#pragma unroll
                for (int mi = 0; mi < 4; mi++)
#pragma unroll
                    for (int j = 0; j < 4; j++) {
                        float m = Mreg[mi][j & 1];
                        __half2 hv = *(__half2*)&af[mi][j];
                        float2 f = __half22float2(hv);
                        f.x = __expf(f.x - m);
                        f.y = __expf(f.y - m);
                        __half2 ho = __floats2half2_rn(f.x, f.y);
                        af[mi][j] = *(uint32_t*)&ho;
                    }
            }
#pragma unroll
            for (int ni = 0; ni < 8; ni++) {
                const uint32_t* p = Bs + (wn + ni * 8 + g) * (ROWH / 2) + kk * 8 + t;
                bf[ni][0] = p[0];
                bf[ni][1] = p[4];
            }
#pragma unroll
            for (int mi = 0; mi < 4; mi++)
#pragma unroll
                for (int ni = 0; ni < 8; ni++) {
                    float* d = acc[mi][ni];
                    asm volatile(
                        "mma.sync.aligned.m16n8k16.row.col.f32.f16.f16.f32 "
                        "{%0,%1,%2,%3}, {%4,%5,%6,%7}, {%8,%9}, {%0,%1,%2,%3};"
                        : "+f"(d[0]), "+f"(d[1]), "+f"(d[2]), "+f"(d[3])
                        : "r"(af[mi][0]), "r"(af[mi][1]), "r"(af[mi][2]), "r"(af[mi][3]),
                          "r"(bf[ni][0]), "r"(bf[ni][1]));
                }
        }
        __syncthreads();
        if (++stage == NSTAGE) stage = 0;
    }

    // ---------------- epilogue ----------------
    if (mode == 0) {
        float* Cb = (float*)Cg + (size_t)b * sC;
#pragma unroll
        for (int mi = 0; mi < 4; mi++)
#pragma unroll
            for (int ni = 0; ni < 8; ni++) {
                int row = m0 + wm + mi * 16 + g;
                int col = n0 + wn + ni * 8 + t * 2;
                float* d = acc[mi][ni];
                float2 v0 = make_float2(d[0], d[1]);
                float2 v1 = make_float2(d[2], d[3]);
                if (bias) {
                    float b0 = bias[row], b1 = bias[row + 8];
                    v0.x += b0; v0.y += b0;
                    v1.x += b1; v1.y += b1;
                }
                if (resid) {
                    const float* R = resid + (size_t)b * sR;
                    float2 r0 = *(const float2*)&R[(size_t)row * ldc + col];
                    float2 r1 = *(const float2*)&R[(size_t)(row + 8) * ldc + col];
                    v0.x += r0.x; v0.y += r0.y;
                    v1.x += r1.x; v1.y += r1.y;
                }
                *(float2*)&Cb[(size_t)row * ldc + col]       = v0;
                *(float2*)&Cb[(size_t)(row + 8) * ldc + col] = v1;
            }
    } else if (mode == 1 || mode == 3) {
        __half* Cb = (__half*)Cg + (size_t)b * sC;
#pragma unroll
        for (int mi = 0; mi < 4; mi++)
#pragma unroll
            for (int ni = 0; ni < 8; ni++) {
                int row = m0 + wm + mi * 16 + g;
                int col = n0 + wn + ni * 8 + t * 2;
                float* d = acc[mi][ni];
                *(__half2*)&Cb[(size_t)row * ldc + col] =
                    __floats2half2_rn(d[0], d[1]);
                *(__half2*)&Cb[(size_t)(row + 8) * ldc + col] =
                    __floats2half2_rn(d[2], d[3]);
            }
        if (mode == 3) {
            // per-tile softmax stats over this CTA's 256 columns
            float2* red = (float2*)sm;        // [128][4]
            const int nw = warp >> 1;         // n-warp index 0..3
#pragma unroll
            for (int mi = 0; mi < 4; mi++)
#pragma unroll
                for (int h = 0; h < 2; h++) {
                    int rl = wm + mi * 16 + g + 8 * h;
                    float lm = -INFINITY;
#pragma unroll
                    for (int ni = 0; ni < 8; ni++)
                        lm = fmaxf(lm, fmaxf(acc[mi][ni][2 * h], acc[mi][ni][2 * h + 1]));
                    lm = fmaxf(lm, __shfl_xor_sync(0xffffffffu, lm, 1));
                    lm = fmaxf(lm, __shfl_xor_sync(0xffffffffu, lm, 2));
                    float ls = 0.f;
#pragma unroll
                    for (int ni = 0; ni < 8; ni++)
                        ls += __expf(acc[mi][ni][2 * h] - lm)
                            + __expf(acc[mi][ni][2 * h + 1] - lm);
                    ls += __shfl_xor_sync(0xffffffffu, ls, 1);
                    ls += __shfl_xor_sync(0xffffffffu, ls, 2);
                    if (t == 0) red[rl * 4 + nw] = make_float2(lm, ls);
                }
            __syncthreads();
            if (tid < 128) {
                float M = -INFINITY;
#pragma unroll
                for (int i = 0; i < 4; i++) M = fmaxf(M, red[tid * 4 + i].x);
                float L = 0.f;
#pragma unroll
                for (int i = 0; i < 4; i++) {
                    float2 v = red[tid * 4 + i];
                    L += v.y * __expf(v.x - M);
                }
                size_t o = ((size_t)b * NTILES + blockIdx.x) * NN + m0 + tid;
                g_Mt[o] = M;
                g_Lt[o] = L;
            }
        }
    } else if (mode == 4) {
        __half* Cb = (__half*)Cg + (size_t)b * sC;
#pragma unroll
        for (int mi = 0; mi < 4; mi++) {
            int r = m0 + wm + mi * 16 + g;
            float li0 = g_Linv[(size_t)b * NN + r];
            float li1 = g_Linv[(size_t)b * NN + r + 8];
#pragma unroll
            for (int ni = 0; ni < 8; ni++) {
                int col = n0 + wn + ni * 8 + t * 2;
                float* d = acc[mi][ni];
                *(__half2*)&Cb[(size_t)r * ldc + col] =
                    __floats2half2_rn(d[0] * li0, d[1] * li0);
                *(__half2*)&Cb[(size_t)(r + 8) * ldc + col] =
                    __floats2half2_rn(d[2] * li1, d[3] * li1);
            }
        }
    } else {
        // mode 2: KV split
        __half* Tb = Ct + (size_t)b * sCt;               // keyT [n][c]
        __half* Vb = (__half*)Cg + (size_t)b * sC;       // val  [c][n]
#pragma unroll
        for (int mi = 0; mi < 4; mi++)
#pragma unroll
            for (int ni = 0; ni < 8; ni++) {
                int row = m0 + wm + mi * 16 + g;
                int col = n0 + wn + ni * 8 + t * 2;
                float* d = acc[mi][ni];
                if (row < CC) {
                    Tb[(size_t)col * ldct + row]           = __float2half_rn(d[0]);
                    Tb[(size_t)(col + 1) * ldct + row]     = __float2half_rn(d[1]);
                    Tb[(size_t)col * ldct + row + 8]       = __float2half_rn(d[2]);
                    Tb[(size_t)(col + 1) * ldct + row + 8] = __float2half_rn(d[3]);
                } else {
                    *(__half2*)&Vb[(size_t)(row - CC) * ldc + col] =
                        __floats2half2_rn(d[0], d[1]);
                    *(__half2*)&Vb[(size_t)(row - CC + 8) * ldc + col] =
                        __floats2half2_rn(d[2], d[3]);
                }
            }
    }
#undef ISSUE
}

// ---------------- merge per-tile stats -> final M, 1/L -----------------------
__global__ void merge_ml() {
    int idx = blockIdx.x * 256 + threadIdx.x;     // b*NN + row
    if (idx >= BB * NN) return;
    int b = idx >> 12, row = idx & (NN - 1);
    const float* Mp = g_Mt + (size_t)b * NTILES * NN + row;
    const float* Lp = g_Lt + (size_t)b * NTILES * NN + row;
    float M = -INFINITY;
#pragma unroll
    for (int i = 0; i < NTILES; i++) M = fmaxf(M, Mp[(size_t)i * NN]);
    float L = 0.f;
#pragma unroll
    for (int i = 0; i < NTILES; i++)
        L += Lp[(size_t)i * NN] * __expf(Mp[(size_t)i * NN] - M);
    g_M[idx] = M;
    g_Linv[idx] = 1.f / L;
}

// ---------------- launch ------------------------------------------------------
extern "C" void kernel_launch(void* const* d_in, const int* in_sizes, int n_in,
                              void* d_out, int out_size) {
    const float* input = (const float*)d_in[0];
    const float* quary = (const float*)d_in[1];
    const float* gw    = (const float*)d_in[2];
    const float* gb    = (const float*)d_in[3];
    const float* wq    = (const float*)d_in[4];
    const float* wkv   = (const float*)d_in[5];
    const float* wout  = (const float*)d_in[6];
    const float* bout  = (const float*)d_in[7];
    float* out = (float*)d_out;

    static int smem_set = 0;
    if (!smem_set) {
        cudaFuncSetAttribute(gemm_tn_f16,
                             cudaFuncAttributeMaxDynamicSharedMemorySize, SMEM_BYTES);
        smem_set = 1;
    }

    __half *p_qT, *p_normT, *p_keyT, *p_val, *p_attn, *p_aoT, *p_wkv, *p_wout;
    cudaGetSymbolAddress((void**)&p_qT,    g_qT);
    cudaGetSymbolAddress((void**)&p_normT, g_normT);
    cudaGetSymbolAddress((void**)&p_keyT,  g_keyT);
    cudaGetSymbolAddress((void**)&p_val,   g_val);
    cudaGetSymbolAddress((void**)&p_attn,  g_attn);
    cudaGetSymbolAddress((void**)&p_aoT,   g_aoT);
    cudaGetSymbolAddress((void**)&p_wkv,   g_wkv_h);
    cudaGetSymbolAddress((void**)&p_wout,  g_wout_h);

    const size_t sCN  = (size_t)CC * NN;
    const size_t sNC  = (size_t)NN * CC;
    const size_t sNNb = (size_t)NN * NN;

    gn_stats<<<BB * GG, 256>>>(input);
    round_w<<<512, 256>>>(wkv, wout);
    q_proj_t<<<(int)(((size_t)BB * NN * CC + 255) / 256), 256>>>(quary, wq);
    norm_t<<<dim3(NN / 32, CC / 32, BB), dim3(32, 8)>>>(input, gw, gb);

    // KV: A = wkv_h [512][256], B = normT -> keyT + val (split)
    gemm_tn_f16<<<dim3(NN / BN, 512 / BM, BB), 256, SMEM_BYTES>>>(
        p_wkv, p_normT, p_val, p_keyT, nullptr, nullptr,
        CC, NN, CC, 2, 0, sNC, sCN, sNC, 0);

    // S = Q^T K + per-tile softmax stats (mode 3)
    gemm_tn_f16<<<dim3(NN / BN, NN / BM, BB), 256, SMEM_BYTES>>>(
        p_qT, p_keyT, p_attn, nullptr, nullptr, nullptr,
        CC, NN, 0, 3, sNC, sNC, sNNb, 0, 0);

    merge_ml<<<(BB * NN) / 256, 256>>>();

    // AO^T = softmax(S) V^T with exp folded into A path (mode 4)
    gemm_tn_f16<<<dim3(CC / BN, NN / BM, BB), 256, SMEM_BYTES>>>(
        p_attn, p_val, p_aoT, nullptr, nullptr, nullptr,
        NN, CC, 0, 4, sNNb, sCN, sNC, 0, 0);

    // out = W_out AO + b + input (fp32)
    gemm_tn_f16<<<dim3(NN / BN, CC / BM, BB), 256, SMEM_BYTES>>>(
        p_wout, p_aoT, out, nullptr, bout, input,
        CC, NN, 0, 0, 0, sNC, sCN, 0, sCN);
}

// round 7
// speedup vs baseline: 1.0568x; 1.0568x over previous
#include <cuda_runtime.h>
#include <cuda_fp16.h>
#include <math.h>
#include <stdint.h>

#define BB 8
#define CC 256
#define NN 4096      // H*W
#define GG 32
#define CPG 8
#define EPSV 1e-5f

// GEMM tiling (fp16 operands, fp32 accum)
#define BM 128
#define BN 256
#define BKH 32                         // K per stage, in half elements
#define PADH 8
#define ROWH (BKH + PADH)              // 40 half = 80 B
#define A_STG_H (BM * ROWH)            // 5120 half
#define B_STG_H (BN * ROWH)            // 10240 half
#define STG_H (A_STG_H + B_STG_H)      // 15360 half = 30720 B
#define NSTAGE 3
#define SMEM_BYTES (NSTAGE * STG_H * 2)  // 92160 B

// ---------------- scratch (device globals) -----------------------------------
__device__ float  g_mean[BB * GG];
__device__ float  g_rstd[BB * GG];
__device__ __half g_qT   [(size_t)BB * NN * CC];   // Q^T  [b][n][c], scaled
__device__ __half g_normT[(size_t)BB * NN * CC];   // GN(x)^T [b][n][c]
__device__ __half g_keyT [(size_t)BB * NN * CC];   // K^T  [b][n][c]
__device__ __half g_val  [(size_t)BB * CC * NN];   // V    [b][c][n]
__device__ __half g_attn [(size_t)BB * NN * NN];   // S/P  [b][m][n]  256 MB
__device__ __half g_aoT  [(size_t)BB * NN * CC];   // AO^T [b][n][c]
__device__ __half g_wkv_h[2 * CC * CC];
__device__ __half g_wout_h[CC * CC];

// ---------------- 1. GroupNorm statistics ------------------------------------
__global__ void gn_stats(const float* __restrict__ x) {
    const int bg = blockIdx.x;
    const float* p = x + (size_t)bg * (CPG * NN);
    const int tid = threadIdx.x;
    float s = 0.f, s2 = 0.f;
    for (int i = tid; i < CPG * NN; i += 256) {
        float v = p[i];
        s += v; s2 += v * v;
    }
    __shared__ float sh[256], sh2[256];
    sh[tid] = s; sh2[tid] = s2;
    __syncthreads();
    for (int o = 128; o > 0; o >>= 1) {
        if (tid < o) { sh[tid] += sh[tid + o]; sh2[tid] += sh2[tid + o]; }
        __syncthreads();
    }
    if (tid == 0) {
        const float inv_n = 1.f / (CPG * NN);
        float m   = sh[0] * inv_n;
        float var = sh2[0] * inv_n - m * m;
        g_mean[bg] = m;
        g_rstd[bg] = rsqrtf(var + EPSV);
    }
}

// ---------------- 2. weights -> fp16 -----------------------------------------
__global__ void round_w(const float* __restrict__ wkv,
                        const float* __restrict__ wout) {
    int i = blockIdx.x * 256 + threadIdx.x;
    if (i < 2 * CC * CC) g_wkv_h[i] = __float2half_rn(wkv[i]);
    if (i < CC * CC)     g_wout_h[i] = __float2half_rn(wout[i]);
}

// ---------------- 3. Q projection, transposed + scaled -> fp16 ---------------
__global__ void q_proj_t(const float* __restrict__ qin,   // [B,3,N]
                         const float* __restrict__ wq) {  // [C,3]
    size_t idx = (size_t)blockIdx.x * 256 + threadIdx.x;
    if (idx >= (size_t)BB * NN * CC) return;
    int c = (int)(idx & (CC - 1));
    int n = (int)((idx >> 8) & (NN - 1));
    int b = (int)(idx >> 20);
    const float* qb = qin + (size_t)b * 3 * NN + n;
    g_qT[idx] = __float2half_rn(0.0625f * (wq[c * 3 + 0] * qb[0]
                                         + wq[c * 3 + 1] * qb[NN]
                                         + wq[c * 3 + 2] * qb[2 * NN]));
}

// ---------------- 4. GroupNorm apply + transpose -> fp16 ---------------------
__global__ void __launch_bounds__(256) norm_t(const float* __restrict__ x,
                                              const float* __restrict__ gamma,
                                              const float* __restrict__ beta) {
    __shared__ float t[32][33];
    const int b  = blockIdx.z;
    const int n0 = blockIdx.x * 32, c0 = blockIdx.y * 32;
    const int tx = threadIdx.x, ty = threadIdx.y;
#pragma unroll
    for (int i = 0; i < 4; i++) {
        int c  = c0 + ty + i * 8;
        int bg = b * GG + (c >> 3);
        float sc = g_rstd[bg] * gamma[c];
        float sh = beta[c] - g_mean[bg] * sc;
        float v = x[((size_t)b * CC + c) * NN + n0 + tx];
        t[ty + i * 8][tx] = v * sc + sh;
    }
    __syncthreads();
#pragma unroll
    for (int i = 0; i < 4; i++) {
        int n = n0 + ty + i * 8;
        g_normT[((size_t)b * NN + n) * CC + c0 + tx] =
            __float2half_rn(t[tx][ty + i * 8]);
    }
}

// ---------------- generic TN fp16 tensor-core GEMM (cp.async + ldmatrix) -----
// C[m][n] = sum_k A[m][k] * B[n][k]; A,B fp16 k-contiguous.
// mode 0: fp32 out + bias + resid
// mode 1: fp16 out
// mode 2: KV split -> keyT (transposed) + val
#define CP16(d, s) asm volatile("cp.async.cg.shared.global [%0], [%1], 16;" :: "r"(d), "l"(s))
#define LDM4(r0, r1, r2, r3, a)                                              \
    asm volatile("ldmatrix.sync.aligned.m8n8.x4.shared.b16 {%0,%1,%2,%3}, [%4];" \
                 : "=r"(r0), "=r"(r1), "=r"(r2), "=r"(r3) : "r"(a))

__global__ void __launch_bounds__(256) gemm_tn_f16(
    const __half* __restrict__ Ag, const __half* __restrict__ Bg,
    void* __restrict__ Cg, __half* __restrict__ Ct,
    const float* __restrict__ bias, const float* __restrict__ resid,
    int K, int ldc, int ldct, int mode,
    size_t sA, size_t sB, size_t sC, size_t sCt, size_t sR)
{
    extern __shared__ __half sm[];
    const int b = blockIdx.z;
    const __half* A = Ag + (size_t)b * sA;
    const __half* B = Bg + (size_t)b * sB;
    const int m0 = blockIdx.y * BM;
    const int n0 = blockIdx.x * BN;

    const int tid  = threadIdx.x;
    const int lane = tid & 31;
    const int warp = tid >> 5;
    const int wm = (warp & 1) * 64;
    const int wn = (warp >> 1) * 64;
    const int g = lane >> 2, t = lane & 3;

    // cp.async mapping: 4 threads/row, 16B (8 half) each
    const int r4 = tid >> 2;           // 0..63
    const int c8 = (tid & 3) * 8;      // half offset within row
    const __half* Ap = A + (size_t)(m0 + r4) * K + c8;
    const __half* Bp = B + (size_t)(n0 + r4) * K + c8;
    const uint32_t sbase = (uint32_t)__cvta_generic_to_shared(sm);

    // ldmatrix per-thread addressing: lr = row-in-8, lsel = matrix index
    const int lr   = lane & 7;
    const int lsel = lane >> 3;                 // 0..3
    const int lrow = (lsel & 1) * 8 + lr;       // row offset within 16
    const int lkh  = (lsel >> 1) * 8;           // k-half offset (halves)
    // byte offsets within a stage
    const uint32_t a_off0 = (uint32_t)((wm + lrow) * ROWH + lkh) * 2;
    const uint32_t b_off0 = (uint32_t)(A_STG_H + (wn + lrow) * ROWH + lkh) * 2;

#define ISSUE(s, ko)                                                          \
    do {                                                                      \
        uint32_t as_ = sbase + (uint32_t)(s) * (STG_H * 2);                   \
        uint32_t bs_ = as_ + A_STG_H * 2;                                     \
        const __half* ap_ = Ap + (ko);                                        \
        const __half* bp_ = Bp + (ko);                                        \
        CP16(as_ + (r4 * ROWH + c8) * 2,         ap_);                        \
        CP16(as_ + ((r4 + 64) * ROWH + c8) * 2,  ap_ + (size_t)64 * K);       \
        CP16(bs_ + (r4 * ROWH + c8) * 2,         bp_);                        \
        CP16(bs_ + ((r4 + 64) * ROWH + c8) * 2,  bp_ + (size_t)64 * K);       \
        CP16(bs_ + ((r4 + 128) * ROWH + c8) * 2, bp_ + (size_t)128 * K);      \
        CP16(bs_ + ((r4 + 192) * ROWH + c8) * 2, bp_ + (size_t)192 * K);      \
        asm volatile("cp.async.commit_group;");                               \
    } while (0)

    float acc[4][8][4];
#pragma unroll
    for (int mi = 0; mi < 4; mi++)
#pragma unroll
        for (int ni = 0; ni < 8; ni++)
#pragma unroll
            for (int r = 0; r < 4; r++) acc[mi][ni][r] = 0.f;

    const int iters = K / BKH;
    ISSUE(0, 0);
    ISSUE(1, BKH);

    int stage = 0;
    for (int it = 0; it < iters; ++it) {
        if (it + 2 < iters) {
            int s2 = stage + 2; if (s2 >= NSTAGE) s2 -= NSTAGE;
            ISSUE(s2, (size_t)(it + 2) * BKH);
            asm volatile("cp.async.wait_group 2;");
        } else if (it + 1 < iters) {
            asm volatile("cp.async.wait_group 1;");
        } else {
            asm volatile("cp.async.wait_group 0;");
        }
        __syncthreads();

        const uint32_t stg = sbase + (uint32_t)stage * (STG_H * 2);
        const uint32_t aaddr = stg + a_off0;
        const uint32_t baddr = stg + b_off0;

#pragma unroll
        for (int kk = 0; kk < 2; kk++) {            // two k16 steps
            uint32_t af[4][4], bf[8][2];
#pragma unroll
            for (int mi = 0; mi < 4; mi++)
                LDM4(af[mi][0], af[mi][1], af[mi][2], af[mi][3],
                     aaddr + (uint32_t)(mi * 16 * ROWH + kk * 16) * 2);
#pragma unroll
            for (int p = 0; p < 4; p++)
                LDM4(bf[2 * p][0], bf[2 * p + 1][0], bf[2 * p][1], bf[2 * p + 1][1],
                     baddr + (uint32_t)(p * 16 * ROWH + kk * 16) * 2);
#pragma unroll
            for (int mi = 0; mi < 4; mi++)
#pragma unroll
                for (int ni = 0; ni < 8; ni++) {
                    float* d = acc[mi][ni];
                    asm volatile(
                        "mma.sync.aligned.m16n8k16.row.col.f32.f16.f16.f32 "
                        "{%0,%1,%2,%3}, {%4,%5,%6,%7}, {%8,%9}, {%0,%1,%2,%3};"
                        : "+f"(d[0]), "+f"(d[1]), "+f"(d[2]), "+f"(d[3])
                        : "r"(af[mi][0]), "r"(af[mi][1]), "r"(af[mi][2]), "r"(af[mi][3]),
                          "r"(bf[ni][0]), "r"(bf[ni][1]));
                }
        }
        __syncthreads();
        if (++stage == NSTAGE) stage = 0;
    }

    // ---------------- epilogue ----------------
    if (mode == 0) {
        float* Cb = (float*)Cg + (size_t)b * sC;
#pragma unroll
        for (int mi = 0; mi < 4; mi++)
#pragma unroll
            for (int ni = 0; ni < 8; ni++) {
                int row = m0 + wm + mi * 16 + g;
                int col = n0 + wn + ni * 8 + t * 2;
                float* d = acc[mi][ni];
                float2 v0 = make_float2(d[0], d[1]);
                float2 v1 = make_float2(d[2], d[3]);
                if (bias) {
                    float b0 = bias[row], b1 = bias[row + 8];
                    v0.x += b0; v0.y += b0;
                    v1.x += b1; v1.y += b1;
                }
                if (resid) {
                    const float* R = resid + (size_t)b * sR;
                    float2 r0 = *(const float2*)&R[(size_t)row * ldc + col];
                    float2 r1 = *(const float2*)&R[(size_t)(row + 8) * ldc + col];
                    v0.x += r0.x; v0.y += r0.y;
                    v1.x += r1.x; v1.y += r1.y;
                }
                *(float2*)&Cb[(size_t)row * ldc + col]       = v0;
                *(float2*)&Cb[(size_t)(row + 8) * ldc + col] = v1;
            }
    } else if (mode == 1) {
        __half* Cb = (__half*)Cg + (size_t)b * sC;
#pragma unroll
        for (int mi = 0; mi < 4; mi++)
#pragma unroll
            for (int ni = 0; ni < 8; ni++) {
                int row = m0 + wm + mi * 16 + g;
                int col = n0 + wn + ni * 8 + t * 2;
                float* d = acc[mi][ni];
                *(__half2*)&Cb[(size_t)row * ldc + col] =
                    __floats2half2_rn(d[0], d[1]);
                *(__half2*)&Cb[(size_t)(row + 8) * ldc + col] =
                    __floats2half2_rn(d[2], d[3]);
            }
    } else {
        // mode 2: KV split (uniform per block: m0 either < CC or >= CC)
        __half* Tb = Ct + (size_t)b * sCt;               // keyT [n][c]
        __half* Vb = (__half*)Cg + (size_t)b * sC;       // val  [c][n]
#pragma unroll
        for (int mi = 0; mi < 4; mi++)
#pragma unroll
            for (int ni = 0; ni < 8; ni++) {
                int row = m0 + wm + mi * 16 + g;
                int col = n0 + wn + ni * 8 + t * 2;
                float* d = acc[mi][ni];
                if (row < CC) {
                    Tb[(size_t)col * ldct + row]           = __float2half_rn(d[0]);
                    Tb[(size_t)(col + 1) * ldct + row]     = __float2half_rn(d[1]);
                    Tb[(size_t)col * ldct + row + 8]       = __float2half_rn(d[2]);
                    Tb[(size_t)(col + 1) * ldct + row + 8] = __float2half_rn(d[3]);
                } else {
                    *(__half2*)&Vb[(size_t)(row - CC) * ldc + col] =
                        __floats2half2_rn(d[0], d[1]);
                    *(__half2*)&Vb[(size_t)(row - CC + 8) * ldc + col] =
                        __floats2half2_rn(d[2], d[3]);
                }
            }
    }
#undef ISSUE
}

// ---------------- row softmax (rows of 4096 fp16) ----------------------------
__global__ void __launch_bounds__(256) softmax_k() {
    const size_t row = blockIdx.x;
    uint4* p = (uint4*)(g_attn + row * NN);   // 512 uint4 per row
    const int tid = threadIdx.x;
    const int lane = tid & 31, wid = tid >> 5;
    __shared__ float sh[8];

    uint4 raw[2];
    float v[16];
#pragma unroll
    for (int i = 0; i < 2; i++) raw[i] = p[tid + i * 256];
#pragma unroll
    for (int i = 0; i < 2; i++) {
        const __half2* h = (const __half2*)&raw[i];
#pragma unroll
        for (int j = 0; j < 4; j++) {
            float2 f = __half22float2(h[j]);
            v[i * 8 + j * 2]     = f.x;
            v[i * 8 + j * 2 + 1] = f.y;
        }
    }
    float mx = v[0];
#pragma unroll
    for (int i = 1; i < 16; i++) mx = fmaxf(mx, v[i]);
#pragma unroll
    for (int o = 16; o > 0; o >>= 1)
        mx = fmaxf(mx, __shfl_xor_sync(0xffffffffu, mx, o));
    if (lane == 0) sh[wid] = mx;
    __syncthreads();
    mx = sh[0];
#pragma unroll
    for (int i = 1; i < 8; i++) mx = fmaxf(mx, sh[i]);

    float s = 0.f;
#pragma unroll
    for (int i = 0; i < 16; i++) {
        v[i] = __expf(v[i] - mx);
        s += v[i];
    }
#pragma unroll
    for (int o = 16; o > 0; o >>= 1)
        s += __shfl_xor_sync(0xffffffffu, s, o);
    __syncthreads();
    if (lane == 0) sh[wid] = s;
    __syncthreads();
    s = 0.f;
#pragma unroll
    for (int i = 0; i < 8; i++) s += sh[i];
    float inv = 1.f / s;

#pragma unroll
    for (int i = 0; i < 2; i++) {
        __half2* h = (__half2*)&raw[i];
#pragma unroll
        for (int j = 0; j < 4; j++)
            h[j] = __floats2half2_rn(v[i * 8 + j * 2] * inv,
                                     v[i * 8 + j * 2 + 1] * inv);
        p[tid + i * 256] = raw[i];
    }
}

// ---------------- launch ------------------------------------------------------
extern "C" void kernel_launch(void* const* d_in, const int* in_sizes, int n_in,
                              void* d_out, int out_size) {
    const float* input = (const float*)d_in[0];
    const float* quary = (const float*)d_in[1];
    const float* gw    = (const float*)d_in[2];
    const float* gb    = (const float*)d_in[3];
    const float* wq    = (const float*)d_in[4];
    const float* wkv   = (const float*)d_in[5];
    const float* wout  = (const float*)d_in[6];
    const float* bout  = (const float*)d_in[7];
    float* out = (float*)d_out;

    static int smem_set = 0;
    if (!smem_set) {
        cudaFuncSetAttribute(gemm_tn_f16,
                             cudaFuncAttributeMaxDynamicSharedMemorySize, SMEM_BYTES);
        smem_set = 1;
    }

    __half *p_qT, *p_normT, *p_keyT, *p_val, *p_attn, *p_aoT, *p_wkv, *p_wout;
    cudaGetSymbolAddress((void**)&p_qT,    g_qT);
    cudaGetSymbolAddress((void**)&p_normT, g_normT);
    cudaGetSymbolAddress((void**)&p_keyT,  g_keyT);
    cudaGetSymbolAddress((void**)&p_val,   g_val);
    cudaGetSymbolAddress((void**)&p_attn,  g_attn);
    cudaGetSymbolAddress((void**)&p_aoT,   g_aoT);
    cudaGetSymbolAddress((void**)&p_wkv,   g_wkv_h);
    cudaGetSymbolAddress((void**)&p_wout,  g_wout_h);

    const size_t sCN  = (size_t)CC * NN;
    const size_t sNC  = (size_t)NN * CC;
    const size_t sNNb = (size_t)NN * NN;

    gn_stats<<<BB * GG, 256>>>(input);
    round_w<<<512, 256>>>(wkv, wout);
    q_proj_t<<<(int)(((size_t)BB * NN * CC + 255) / 256), 256>>>(quary, wq);
    norm_t<<<dim3(NN / 32, CC / 32, BB), dim3(32, 8)>>>(input, gw, gb);

    // KV: A = wkv_h [512][256], B = normT -> keyT + val (split)
    gemm_tn_f16<<<dim3(NN / BN, 512 / BM, BB), 256, SMEM_BYTES>>>(
        p_wkv, p_normT, p_val, p_keyT, nullptr, nullptr,
        CC, NN, CC, 2, 0, sNC, sCN, sNC, 0);

    // S = Q^T K : A = qT, B = keyT -> attn fp16 [m][n]
    gemm_tn_f16<<<dim3(NN / BN, NN / BM, BB), 256, SMEM_BYTES>>>(
        p_qT, p_keyT, p_attn, nullptr, nullptr, nullptr,
        CC, NN, 0, 1, sNC, sNC, sNNb, 0, 0);

    softmax_k<<<BB * NN, 256>>>();

    // AO^T: A = P [q][j], B = val [c][j] -> aoT fp16 [q][c]
    gemm_tn_f16<<<dim3(CC / BN, NN / BM, BB), 256, SMEM_BYTES>>>(
        p_attn, p_val, p_aoT, nullptr, nullptr, nullptr,
        NN, CC, 0, 1, sNNb, sCN, sNC, 0, 0);

    // out = W_out AO + b + input (fp32)
    gemm_tn_f16<<<dim3(NN / BN, CC / BM, BB), 256, SMEM_BYTES>>>(
        p_wout, p_aoT, out, nullptr, bout, input,
        CC, NN, 0, 0, 0, sNC, sCN, 0, sCN);
}

// round 14
// speedup vs baseline: 1.8299x; 1.7316x over previous
#include <cuda_runtime.h>
#include <cuda_fp16.h>
#include <math.h>
#include <stdint.h>

#define BB 8
#define CC 256
#define NN 4096      // H*W
#define GG 32
#define CPG 8
#define EPSV 1e-5f

// ---------- SIMT GEMM tiling (R4 exact; V proj, PV, out proj) ----------------
#define BM 128
#define BN 256
#define BKH 32
#define PADH 8
#define ROWH (BKH + PADH)              // 40 half = 80 B
#define A_STG_H (BM * ROWH)
#define B_STG_H (BN * ROWH)
#define STG_H (A_STG_H + B_STG_H)      // 15360 half
#define SMEM_BYTES (2 * STG_H * 2)     // 61440 B

#define QK_SMEM (3 * NN * 4 + 128)     // W tile + qv + red

// ---------------- scratch (device globals) -----------------------------------
__device__ float  g_mean[BB * GG];
__device__ float  g_rstd[BB * GG];
__device__ float  g_wqe [3 * CC];                  // wq^T * W_k, scaled 1/16
__device__ float  g_W   [(size_t)BB * 3 * NN];     // wq_eff @ norm  [b][r][n]
__device__ __half g_normT[(size_t)BB * NN * CC];   // GN(x)^T [b][n][c]
__device__ __half g_val  [(size_t)BB * CC * NN];   // V    [b][c][n]
__device__ __half g_attn [(size_t)BB * NN * NN];   // P    [b][m][n]  256 MB
__device__ __half g_aoT  [(size_t)BB * NN * CC];   // AO^T [b][n][c]
__device__ __half g_wkv_h[2 * CC * CC];
__device__ __half g_wout_h[CC * CC];

// ---------------- 1. GroupNorm statistics ------------------------------------
__global__ void gn_stats(const float* __restrict__ x) {
    const int bg = blockIdx.x;
    const float* p = x + (size_t)bg * (CPG * NN);
    const int tid = threadIdx.x;
    float s = 0.f, s2 = 0.f;
    for (int i = tid; i < CPG * NN; i += 256) {
        float v = p[i];
        s += v; s2 += v * v;
    }
    __shared__ float sh[256], sh2[256];
    sh[tid] = s; sh2[tid] = s2;
    __syncthreads();
    for (int o = 128; o > 0; o >>= 1) {
        if (tid < o) { sh[tid] += sh[tid + o]; sh2[tid] += sh2[tid + o]; }
        __syncthreads();
    }
    if (tid == 0) {
        const float inv_n = 1.f / (CPG * NN);
        float m   = sh[0] * inv_n;
        float var = sh2[0] * inv_n - m * m;
        g_mean[bg] = m;
        g_rstd[bg] = rsqrtf(var + EPSV);
    }
}

// ---------------- 2. weights -> fp16 -----------------------------------------
__global__ void round_w(const float* __restrict__ wkv,
                        const float* __restrict__ wout) {
    int i = blockIdx.x * 256 + threadIdx.x;
    if (i < 2 * CC * CC) g_wkv_h[i] = __float2half_rn(wkv[i]);
    if (i < CC * CC)     g_wout_h[i] = __float2half_rn(wout[i]);
}

// ---------------- 2b. wq_eff[r][c] = (1/16) sum_ck wq[ck][r] wkv[ck][c] ------
__global__ void prep_wq(const float* __restrict__ wq,
                        const float* __restrict__ wkv) {
    int c = threadIdx.x;                 // 256 threads, one block
    float s0 = 0.f, s1 = 0.f, s2 = 0.f;
    for (int ck = 0; ck < CC; ck++) {
        float w = wkv[ck * CC + c];      // key rows are wkv[0:256]
        s0 += wq[ck * 3 + 0] * w;
        s1 += wq[ck * 3 + 1] * w;
        s2 += wq[ck * 3 + 2] * w;
    }
    g_wqe[c]           = 0.0625f * s0;
    g_wqe[CC + c]      = 0.0625f * s1;
    g_wqe[2 * CC + c]  = 0.0625f * s2;
}

// ---------------- 3. GroupNorm apply + transpose -> fp16 ---------------------
__global__ void __launch_bounds__(256) norm_t(const float* __restrict__ x,
                                              const float* __restrict__ gamma,
                                              const float* __restrict__ beta) {
    __shared__ float t[32][33];
    const int b  = blockIdx.z;
    const int n0 = blockIdx.x * 32, c0 = blockIdx.y * 32;
    const int tx = threadIdx.x, ty = threadIdx.y;
#pragma unroll
    for (int i = 0; i < 4; i++) {
        int c  = c0 + ty + i * 8;
        int bg = b * GG + (c >> 3);
        float sc = g_rstd[bg] * gamma[c];
        float sh = beta[c] - g_mean[bg] * sc;
        float v = x[((size_t)b * CC + c) * NN + n0 + tx];
        t[ty + i * 8][tx] = v * sc + sh;
    }
    __syncthreads();
#pragma unroll
    for (int i = 0; i < 4; i++) {
        int n = n0 + ty + i * 8;
        g_normT[((size_t)b * NN + n) * CC + c0 + tx] =
            __float2half_rn(t[tx][ty + i * 8]);
    }
}

// ---------------- 4. W[b][r][n] = sum_c wq_eff[r][c] * normT[b][n][c] --------
__global__ void __launch_bounds__(256) compute_W() {
    __shared__ float e0[CC], e1[CC], e2[CC];
    const int tid = threadIdx.x;
    e0[tid] = g_wqe[tid];
    e1[tid] = g_wqe[CC + tid];
    e2[tid] = g_wqe[2 * CC + tid];
    __syncthreads();

    const int b = blockIdx.y;
    const int n = blockIdx.x * 256 + tid;
    const uint4* nr = (const uint4*)(g_normT + ((size_t)b * NN + n) * CC);
    float w0 = 0.f, w1 = 0.f, w2 = 0.f;
#pragma unroll
    for (int i = 0; i < 32; i++) {
        uint4 u = nr[i];
        const __half2* h = (const __half2*)&u;
#pragma unroll
        for (int j = 0; j < 4; j++) {
            float2 f = __half22float2(h[j]);
            int c = i * 8 + j * 2;
            w0 += f.x * e0[c] + f.y * e0[c + 1];
            w1 += f.x * e1[c] + f.y * e1[c + 1];
            w2 += f.x * e2[c] + f.y * e2[c + 1];
        }
    }
    size_t base = (size_t)b * 3 * NN + n;
    g_W[base]          = w0;
    g_W[base + NN]     = w1;
    g_W[base + 2 * NN] = w2;
}

// ---------------- 5. fused S + softmax -> P (fp16) ---------------------------
// S[m][n] = q0[m] W0[n] + q1[m] W1[n] + q2[m] W2[n]; P = softmax_n(S).
// No max subtraction: |S| < ~10 by construction, exp is safe in fp32.
__global__ void __launch_bounds__(256) qk_softmax(const float* __restrict__ quary) {
    extern __shared__ float sW[];                 // [3*NN] + qv[24] + red[8]
    float* qv  = sW + 3 * NN;
    float* red = qv + 24;
    const int tid = threadIdx.x;
    const int lane = tid & 31, wid = tid >> 5;
    const int b  = blockIdx.y;
    const int m0 = blockIdx.x * 8;

    const float4* Wb = (const float4*)(g_W + (size_t)b * 3 * NN);
#pragma unroll
    for (int i = 0; i < 12; i++)
        ((float4*)sW)[tid + i * 256] = Wb[tid + i * 256];
    if (tid < 24) {
        int row = tid / 3, r = tid % 3;
        qv[tid] = quary[((size_t)b * 3 + r) * NN + m0 + row];
    }
    __syncthreads();

    for (int row = 0; row < 8; row++) {
        float q0 = qv[row * 3], q1 = qv[row * 3 + 1], q2 = qv[row * 3 + 2];
        float e[16];
        float l = 0.f;
#pragma unroll
        for (int i = 0; i < 8; i++) {
            int c0 = 2 * tid + i * 512;
            float s0 = q0 * sW[c0]     + q1 * sW[NN + c0]     + q2 * sW[2 * NN + c0];
            float s1 = q0 * sW[c0 + 1] + q1 * sW[NN + c0 + 1] + q2 * sW[2 * NN + c0 + 1];
            float v0 = __expf(s0), v1 = __expf(s1);
            e[2 * i] = v0; e[2 * i + 1] = v1;
            l += v0 + v1;
        }
#pragma unroll
        for (int o = 16; o > 0; o >>= 1)
            l += __shfl_xor_sync(0xffffffffu, l, o);
        if (lane == 0) red[wid] = l;
        __syncthreads();
        l = 0.f;
#pragma unroll
        for (int i = 0; i < 8; i++) l += red[i];
        float inv = 1.f / l;

        __half2* P = (__half2*)(g_attn + ((size_t)b * NN + m0 + row) * NN);
#pragma unroll
        for (int i = 0; i < 8; i++)
            P[tid + i * 256] = __floats2half2_rn(e[2 * i] * inv, e[2 * i + 1] * inv);
        __syncthreads();
    }
}

// ---------------- SIMT TN fp16 GEMM (R4 exact; modes 0 and 1) ----------------
#define CP16(d, s) asm volatile("cp.async.cg.shared.global [%0], [%1], 16;" :: "r"(d), "l"(s))

__global__ void __launch_bounds__(256) gemm_tn_f16(
    const __half* __restrict__ Ag, const __half* __restrict__ Bg,
    void* __restrict__ Cg,
    const float* __restrict__ bias, const float* __restrict__ resid,
    int K, int ldc, int mode,
    size_t sA, size_t sB, size_t sC, size_t sR)
{
    extern __shared__ __half sm[];
    const int b = blockIdx.z;
    const __half* A = Ag + (size_t)b * sA;
    const __half* B = Bg + (size_t)b * sB;
    const int m0 = blockIdx.y * BM;
    const int n0 = blockIdx.x * BN;

    const int tid  = threadIdx.x;
    const int lane = tid & 31;
    const int warp = tid >> 5;
    const int wm = (warp & 1) * 64;
    const int wn = (warp >> 1) * 64;
    const int g = lane >> 2, t = lane & 3;

    const int r4 = tid >> 2;
    const int c8 = (tid & 3) * 8;
    const __half* Ap = A + (size_t)(m0 + r4) * K + c8;
    const __half* Bp = B + (size_t)(n0 + r4) * K + c8;
    const uint32_t sbase = (uint32_t)__cvta_generic_to_shared(sm);

#define ISSUE(s, ko)                                                          \
    do {                                                                      \
        uint32_t as_ = sbase + (uint32_t)(s) * (STG_H * 2);                   \
        uint32_t bs_ = as_ + A_STG_H * 2;                                     \
        const __half* ap_ = Ap + (ko);                                        \
        const __half* bp_ = Bp + (ko);                                        \
        CP16(as_ + (r4 * ROWH + c8) * 2,         ap_);                        \
        CP16(as_ + ((r4 + 64) * ROWH + c8) * 2,  ap_ + (size_t)64 * K);       \
        CP16(bs_ + (r4 * ROWH + c8) * 2,         bp_);                        \
        CP16(bs_ + ((r4 + 64) * ROWH + c8) * 2,  bp_ + (size_t)64 * K);       \
        CP16(bs_ + ((r4 + 128) * ROWH + c8) * 2, bp_ + (size_t)128 * K);      \
        CP16(bs_ + ((r4 + 192) * ROWH + c8) * 2, bp_ + (size_t)192 * K);      \
        asm volatile("cp.async.commit_group;");                               \
    } while (0)

    float acc[4][8][4];
#pragma unroll
    for (int mi = 0; mi < 4; mi++)
#pragma unroll
        for (int ni = 0; ni < 8; ni++)
#pragma unroll
            for (int r = 0; r < 4; r++) acc[mi][ni][r] = 0.f;

    const int iters = K / BKH;
    ISSUE(0, 0);
    ISSUE(1, BKH);
    asm volatile("cp.async.wait_group 1;");
    __syncthreads();

    for (int it = 0; it < iters; ++it) {
        const uint32_t* As = (const uint32_t*)(sm + (it & 1) * STG_H);
        const uint32_t* Bs = As + (A_STG_H >> 1);

#pragma unroll
        for (int kk = 0; kk < 2; kk++) {
            uint32_t af[4][4], bf[8][2];
#pragma unroll
            for (int mi = 0; mi < 4; mi++) {
                const uint32_t* p = As + (wm + mi * 16 + g) * (ROWH / 2) + kk * 8 + t;
                af[mi][0] = p[0];
                af[mi][1] = p[8 * (ROWH / 2)];
                af[mi][2] = p[4];
                af[mi][3] = p[8 * (ROWH / 2) + 4];
            }
#pragma unroll
            for (int ni = 0; ni < 8; ni++) {
                const uint32_t* p = Bs + (wn + ni * 8 + g) * (ROWH / 2) + kk * 8 + t;
                bf[ni][0] = p[0];
                bf[ni][1] = p[4];
            }
#pragma unroll
            for (int mi = 0; mi < 4; mi++)
#pragma unroll
                for (int ni = 0; ni < 8; ni++) {
                    float* d = acc[mi][ni];
                    asm volatile(
                        "mma.sync.aligned.m16n8k16.row.col.f32.f16.f16.f32 "
                        "{%0,%1,%2,%3}, {%4,%5,%6,%7}, {%8,%9}, {%0,%1,%2,%3};"
                        : "+f"(d[0]), "+f"(d[1]), "+f"(d[2]), "+f"(d[3])
                        : "r"(af[mi][0]), "r"(af[mi][1]), "r"(af[mi][2]), "r"(af[mi][3]),
                          "r"(bf[ni][0]), "r"(bf[ni][1]));
                }
        }
        __syncthreads();
        if (it + 2 < iters) {
            ISSUE(it & 1, (size_t)(it + 2) * BKH);
            asm volatile("cp.async.wait_group 1;");
        } else {
            asm volatile("cp.async.wait_group 0;");
        }
        __syncthreads();
    }

    if (mode == 0) {
        float* Cb = (float*)Cg + (size_t)b * sC;
#pragma unroll
        for (int mi = 0; mi < 4; mi++)
#pragma unroll
            for (int ni = 0; ni < 8; ni++) {
                int row = m0 + wm + mi * 16 + g;
                int col = n0 + wn + ni * 8 + t * 2;
                float* d = acc[mi][ni];
                float2 v0 = make_float2(d[0], d[1]);
                float2 v1 = make_float2(d[2], d[3]);
                if (bias) {
                    float b0 = bias[row], b1 = bias[row + 8];
                    v0.x += b0; v0.y += b0;
                    v1.x += b1; v1.y += b1;
                }
                if (resid) {
                    const float* R = resid + (size_t)b * sR;
                    float2 r0 = *(const float2*)&R[(size_t)row * ldc + col];
                    float2 r1 = *(const float2*)&R[(size_t)(row + 8) * ldc + col];
                    v0.x += r0.x; v0.y += r0.y;
                    v1.x += r1.x; v1.y += r1.y;
                }
                *(float2*)&Cb[(size_t)row * ldc + col]       = v0;
                *(float2*)&Cb[(size_t)(row + 8) * ldc + col] = v1;
            }
    } else {
        __half* Cb = (__half*)Cg + (size_t)b * sC;
#pragma unroll
        for (int mi = 0; mi < 4; mi++)
#pragma unroll
            for (int ni = 0; ni < 8; ni++) {
                int row = m0 + wm + mi * 16 + g;
                int col = n0 + wn + ni * 8 + t * 2;
                float* d = acc[mi][ni];
                *(__half2*)&Cb[(size_t)row * ldc + col] =
                    __floats2half2_rn(d[0], d[1]);
                *(__half2*)&Cb[(size_t)(row + 8) * ldc + col] =
                    __floats2half2_rn(d[2], d[3]);
            }
    }
#undef ISSUE
}

// ---------------- launch ------------------------------------------------------
extern "C" void kernel_launch(void* const* d_in, const int* in_sizes, int n_in,
                              void* d_out, int out_size) {
    const float* input = (const float*)d_in[0];
    const float* quary = (const float*)d_in[1];
    const float* gw    = (const float*)d_in[2];
    const float* gb    = (const float*)d_in[3];
    const float* wq    = (const float*)d_in[4];
    const float* wkv   = (const float*)d_in[5];
    const float* wout  = (const float*)d_in[6];
    const float* bout  = (const float*)d_in[7];
    float* out = (float*)d_out;

    static int smem_set = 0;
    if (!smem_set) {
        cudaFuncSetAttribute(gemm_tn_f16,
                             cudaFuncAttributeMaxDynamicSharedMemorySize, SMEM_BYTES);
        cudaFuncSetAttribute(qk_softmax,
                             cudaFuncAttributeMaxDynamicSharedMemorySize, QK_SMEM);
        smem_set = 1;
    }

    __half *p_normT, *p_val, *p_attn, *p_aoT, *p_wkv, *p_wout;
    cudaGetSymbolAddress((void**)&p_normT, g_normT);
    cudaGetSymbolAddress((void**)&p_val,   g_val);
    cudaGetSymbolAddress((void**)&p_attn,  g_attn);
    cudaGetSymbolAddress((void**)&p_aoT,   g_aoT);
    cudaGetSymbolAddress((void**)&p_wkv,   g_wkv_h);
    cudaGetSymbolAddress((void**)&p_wout,  g_wout_h);

    const size_t sCN  = (size_t)CC * NN;
    const size_t sNC  = (size_t)NN * CC;
    const size_t sNNb = (size_t)NN * NN;

    gn_stats<<<BB * GG, 256>>>(input);
    round_w<<<512, 256>>>(wkv, wout);
    prep_wq<<<1, 256>>>(wq, wkv);
    norm_t<<<dim3(NN / 32, CC / 32, BB), dim3(32, 8)>>>(input, gw, gb);

    // W = wq_eff @ norm  (fp32, [b][3][n])
    compute_W<<<dim3(NN / 256, BB), 256>>>();

    // V = W_v @ norm : A = wkv_h[256:512], B = normT -> val fp16 [c][n]
    gemm_tn_f16<<<dim3(NN / BN, CC / BM, BB), 256, SMEM_BYTES>>>(
        p_wkv + CC * CC, p_normT, p_val, nullptr, nullptr,
        CC, NN, 1, 0, sNC, sCN, 0);

    // P = softmax(quary^T W) fused, fp16 [m][n]
    qk_softmax<<<dim3(NN / 8, BB), 256, QK_SMEM>>>(quary);

    // AO^T: A = P [q][j], B = val [c][j] -> aoT fp16 [q][c]
    gemm_tn_f16<<<dim3(CC / BN, NN / BM, BB), 256, SMEM_BYTES>>>(
        p_attn, p_val, p_aoT, nullptr, nullptr,
        NN, CC, 1, sNNb, sCN, sNC, 0);

    // out = W_out AO + b + input (fp32)
    gemm_tn_f16<<<dim3(NN / BN, CC / BM, BB), 256, SMEM_BYTES>>>(
        p_wout, p_aoT, out, bout, input,
        CC, NN, 0, 0, sNC, sCN, sCN);
}